// round 6
// baseline (speedup 1.0000x reference)
#include <cuda_runtime.h>
#include <cuda_fp16.h>
#include <cstdint>

// patchEmbedding fused: (0) W->fp16 prep; (1) per-CTA gather A tile into smem once,
// then dense fp16 HMMA GEMM over all N=768 with double-buffered B tiles.
//   M = B*T = 131072, K = 256, N = 768
// K pair-permuted per 16-group (pair p -> 2*(p&3)+(p>>2)): each m16n8k16 fragment's
// half-pairs (2tq, 2tq+8) adjacent -> single LDS.64 per fragment.

#define HW    512
#define TDIM  4096
#define EMBD  768
#define KTOT  256
#define BM    128
#define BN    128
#define NNB   6                           // 768 / 128 n-blocks
#define PADC  12

#define SROW  544                         // bytes per smem row: 512 B data + 32 B pad
#define MATB  (128 * SROW)                // 69632 B per matrix tile
#define SM_COORD 0
#define SM_A     1024
#define SM_B     (SM_A + MATB)            // two B stages follow
#define SM_TOTAL (SM_B + 2 * MATB)        // 209920 B

__device__ __align__(16) __half g_Wh[EMBD * KTOT];   // fp16, k-permuted

__device__ __forceinline__ uint32_t s2u(const void* p) {
    uint32_t a;
    asm("{ .reg .u64 t; cvta.to.shared.u64 t, %1; cvt.u32.u64 %0, t; }" : "=r"(a) : "l"(p));
    return a;
}
__device__ __forceinline__ void cp16(uint32_t dst, const void* src) {
    asm volatile("cp.async.ca.shared.global [%0], [%1], 16;" :: "r"(dst), "l"(src) : "memory");
}
__device__ __forceinline__ void mma_f16(float c[4], uint32_t a0, uint32_t a1,
                                        uint32_t a2, uint32_t a3,
                                        uint32_t b0, uint32_t b1) {
    asm volatile(
        "mma.sync.aligned.m16n8k16.row.col.f32.f16.f16.f32 "
        "{%0,%1,%2,%3}, {%4,%5,%6,%7}, {%8,%9}, {%0,%1,%2,%3};"
        : "+f"(c[0]), "+f"(c[1]), "+f"(c[2]), "+f"(c[3])
        : "r"(a0), "r"(a1), "r"(a2), "r"(a3), "r"(b0), "r"(b1));
}
__device__ __forceinline__ int kperm(int k) {        // permute half idx within 16-group
    int p = (k >> 1) & 7;
    return (k & ~15) | ((2 * (p & 3) + (p >> 2)) << 1) | (k & 1);
}

// ---- kernel 0: W -> fp16, k pair-permuted ----
__global__ void prep_w(const float* __restrict__ W) {
    int i = blockIdx.x * blockDim.x + threadIdx.x;
    if (i >= EMBD * KTOT) return;
    g_Wh[(i & ~(KTOT - 1)) | kperm(i & (KTOT - 1))] = __float2half_rn(W[i]);
}

// ---- fused gather + GEMM ----
__global__ void __launch_bounds__(256, 1)
patch_gemm(const float* __restrict__ img,
           const int*   __restrict__ kp,
           const int*   __restrict__ sh,
           const float* __restrict__ bias,
           float*       __restrict__ out)
{
    extern __shared__ char smem[];
    const uint32_t sb = s2u(smem);
    const int tid = threadIdx.x;
    const int wid = tid >> 5;
    const int lid = tid & 31;
    const int m0  = blockIdx.x * BM;

    const int wm = wid & 3;               // 4 m-groups of 32 rows
    const int wn = wid >> 2;              // 2 n-groups of 64 cols
    const int gq = lid >> 2;              // 0..7
    const int tq = lid & 3;               // 0..3

    // ---- coords ----
    int2* coord = (int2*)(smem + SM_COORD);
    if (tid < BM) {
        int2 k = ((const int2*)kp)[m0 + tid];
        int2 s = ((const int2*)sh)[m0 + tid];
        int2 c;
        c.x = k.x + s.x - PADC;           // starts[...,0] = x
        c.y = k.y + s.y - PADC;           // starts[...,1] = y
        coord[tid] = c;
    }

    // ---- B stage loader: 128 rows x 512 B (full K) ----
    #define LOAD_B(buf, nb)                                                        \
        {                                                                          \
            _Pragma("unroll")                                                      \
            for (int i = 0; i < 16; i++) {                                         \
                const int idx = i * 256 + tid;       /* 0..4095 */                 \
                const int row = idx >> 5;                                          \
                const int q   = idx & 31;                                          \
                cp16(sb + SM_B + (buf) * MATB + row * SROW + q * 16,               \
                     g_Wh + (size_t)((nb) * BN + row) * KTOT + q * 8);             \
            }                                                                      \
            asm volatile("cp.async.commit_group;" ::: "memory");                   \
        }

    LOAD_B(0, 0);                         // B0 in flight during the gather

    __syncthreads();                      // coords visible

    // ---- gather A tile (128 patches x 256 px) into smem, fp16 + permuted k ----
    {
        const float* imgb = img + (size_t)(m0 / TDIM) * (HW * HW);
        const int pp = lid & 15;          // pair-slot within a 32-half chunk
        const int h  = pp >> 3;           // image row within chunk
        const int jp = pp & 7;            // x-pair
        const int kdst = h * 16 + (2 * (jp & 3) + (jp >> 2)) * 2;   // permuted

        #pragma unroll 1
        for (int i = 0; i < 8; i++) {
            const int p = i * 16 + wid * 2 + (lid >> 4);
            const int2 c = coord[p];
            char* arow = smem + SM_A + p * SROW + kdst * 2;
            #pragma unroll
            for (int kc = 0; kc < 8; kc++) {
                const int y  = c.y + kc * 2 + h;
                const int x0 = c.x + 2 * jp;
                float v0 = 0.f, v1 = 0.f;
                if ((unsigned)y < HW) {
                    const float* rp = imgb + y * HW;
                    if ((unsigned)(x0)     < HW) v0 = __ldg(rp + x0);
                    if ((unsigned)(x0 + 1) < HW) v1 = __ldg(rp + x0 + 1);
                }
                *(__half2*)(arow + kc * 64) = __floats2half2_rn(v0, v1);
            }
        }
    }
    __syncthreads();                      // A tile complete

    const char* As = smem + SM_A;

    #pragma unroll 1
    for (int nb = 0; nb < NNB; nb++) {
        const int cur = nb & 1;
        asm volatile("cp.async.wait_group 0;" ::: "memory");
        __syncthreads();                  // B(cur) ready; other buffer free

        if (nb + 1 < NNB) LOAD_B(cur ^ 1, nb + 1);

        const char* Bs = smem + SM_B + cur * MATB;
        float acc[2][8][4] = {};

        #pragma unroll
        for (int ks = 0; ks < 16; ks++) {
            const int kb = ks * 32 + 8 * tq;
            uint2 a0[2], a1[2];
            #pragma unroll
            for (int mt = 0; mt < 2; mt++) {
                const int r = wm * 32 + mt * 16 + gq;
                a0[mt] = *(const uint2*)(As + r * SROW + kb);        // {a0a1, a4a5}
                a1[mt] = *(const uint2*)(As + (r + 8) * SROW + kb);  // {a2a3, a6a7}
            }
            #pragma unroll
            for (int nt = 0; nt < 8; nt++) {
                const int n = wn * 64 + nt * 8 + gq;
                const uint2 b = *(const uint2*)(Bs + n * SROW + kb); // {b0b1, b2b3}
                mma_f16(acc[0][nt], a0[0].x, a1[0].x, a0[0].y, a1[0].y, b.x, b.y);
                mma_f16(acc[1][nt], a0[1].x, a1[1].x, a0[1].y, a1[1].y, b.x, b.y);
            }
        }

        // ---- epilogue for this n-block ----
        #pragma unroll
        for (int mt = 0; mt < 2; mt++) {
            const int r0 = m0 + wm * 32 + mt * 16 + gq;
            #pragma unroll
            for (int nt = 0; nt < 8; nt++) {
                const int col = nb * BN + wn * 64 + nt * 8 + tq * 2;
                const float2 bl = *(const float2*)(bias + col);
                float2 o0, o1;
                o0.x = acc[mt][nt][0] + bl.x;
                o0.y = acc[mt][nt][1] + bl.y;
                o1.x = acc[mt][nt][2] + bl.x;
                o1.y = acc[mt][nt][3] + bl.y;
                *(float2*)(out + (size_t)r0 * EMBD + col)       = o0;
                *(float2*)(out + (size_t)(r0 + 8) * EMBD + col) = o1;
            }
        }
        __syncthreads();                  // all reads of B(cur) done before refill
    }
}

extern "C" void kernel_launch(void* const* d_in, const int* in_sizes, int n_in,
                              void* d_out, int out_size)
{
    const float* img  = (const float*)d_in[0];   // [32,1,512,512] f32
    const int*   kp   = (const int*)  d_in[1];   // [32,4096,2] i32
    const int*   sh   = (const int*)  d_in[2];   // [32,4096,2] i32
    const float* Wlin = (const float*)d_in[3];   // [768,256] f32
    const float* blin = (const float*)d_in[4];   // [768] f32
    float*       out  = (float*)d_out;           // [32,4096,768] f32

    prep_w<<<(EMBD * KTOT + 255) / 256, 256>>>(Wlin);

    cudaFuncSetAttribute(patch_gemm,
                         cudaFuncAttributeMaxDynamicSharedMemorySize, SM_TOTAL);
    patch_gemm<<<(32 * TDIM) / BM, 256, SM_TOTAL>>>(img, kp, sh, blin, out);
}

// round 8
// speedup vs baseline: 1.2224x; 1.2224x over previous
#include <cuda_runtime.h>
#include <cuda_fp16.h>
#include <cstdint>

// patchEmbedding: (0) W->fp16 prep, (1) patch gather/pack fp16, (2) dense fp16 HMMA GEMM.
//   M = B*T = 131072, K = 256, N = 768
// K permuted per 32-half group: pair p (0..15) stored at position 4*(p&3)+(p>>2), so a
// thread's pairs {tq, tq+4, tq+8, tq+12} are contiguous -> one LDS.128 yields fragment
// registers for TWO m16n8k16 k-steps. Smem stage rows are 64B, stride 64 (conflict-free).

#define HW    512
#define TDIM  4096
#define EMBD  768
#define KTOT  256
#define BM    128
#define BN    256
#define NKI   8                            // 256 / 32 k-iterations
#define NST   4                            // cp.async stages
#define PADC  12

#define A_ST  (BM * 64)                    // 8192 B per A stage
#define B_ST  (BN * 64)                    // 16384 B per B stage
#define SM_A     0
#define SM_B     (NST * A_ST)              // 32768
#define SM_TOTAL (SM_B + NST * B_ST)       // 98304 B

__device__ __align__(16) __half g_Wh[EMBD * KTOT];        // fp16, k-permuted
__device__ __align__(16) __half g_Apack[131072 * KTOT];   // fp16, k-permuted

__device__ __forceinline__ uint32_t s2u(const void* p) {
    uint32_t a;
    asm("{ .reg .u64 t; cvta.to.shared.u64 t, %1; cvt.u32.u64 %0, t; }" : "=r"(a) : "l"(p));
    return a;
}
__device__ __forceinline__ void cp16(uint32_t dst, const void* src) {
    asm volatile("cp.async.ca.shared.global [%0], [%1], 16;" :: "r"(dst), "l"(src) : "memory");
}
__device__ __forceinline__ void mma_f16(float c[4], uint32_t a0, uint32_t a1,
                                        uint32_t a2, uint32_t a3,
                                        uint32_t b0, uint32_t b1) {
    asm volatile(
        "mma.sync.aligned.m16n8k16.row.col.f32.f16.f16.f32 "
        "{%0,%1,%2,%3}, {%4,%5,%6,%7}, {%8,%9}, {%0,%1,%2,%3};"
        : "+f"(c[0]), "+f"(c[1]), "+f"(c[2]), "+f"(c[3])
        : "r"(a0), "r"(a1), "r"(a2), "r"(a3), "r"(b0), "r"(b1));
}
// permute half index k within its 32-group: pair p=(k>>1)&15 -> 4*(p&3)+(p>>2)
__device__ __forceinline__ int kperm(int k) {
    int p = (k >> 1) & 15;
    return (k & ~31) | ((4 * (p & 3) + (p >> 2)) << 1) | (k & 1);
}

// ---- kernel 0: W -> fp16, k permuted ----
__global__ void prep_w(const float* __restrict__ W) {
    int i = blockIdx.x * blockDim.x + threadIdx.x;
    if (i >= EMBD * KTOT) return;
    g_Wh[(i & ~(KTOT - 1)) | kperm(i & (KTOT - 1))] = __float2half_rn(W[i]);
}

// ---- kernel 1: gather patches -> g_Apack (fp16, k permuted) ----
__global__ void __launch_bounds__(256, 4)
pack_a(const float* __restrict__ img,
       const int*   __restrict__ kp,
       const int*   __restrict__ sh)
{
    __shared__ int2 coord[BM];
    const int tid = threadIdx.x;
    const int wid = tid >> 5;
    const int lid = tid & 31;
    const int m0  = blockIdx.x * BM;

    if (tid < BM) {
        int2 k = ((const int2*)kp)[m0 + tid];
        int2 s = ((const int2*)sh)[m0 + tid];
        int2 c;
        c.x = k.x + s.x - PADC;          // starts[...,0] = x
        c.y = k.y + s.y - PADC;          // starts[...,1] = y
        coord[tid] = c;
    }
    __syncthreads();

    const float* imgb = img + (size_t)(m0 / TDIM) * (HW * HW);
    const int pp = lid & 15;             // pair-slot within a 32-half group
    const int h  = pp >> 3;              // image-row parity within group
    const int jp = pp & 7;               // x-pair
    const int p  = h * 8 + jp;           // pair index within group
    const int kdst = (4 * (p & 3) + (p >> 2)) * 2;   // permuted half offset

    #pragma unroll 1
    for (int i = 0; i < 8; i++) {
        const int pat = i * 16 + wid * 2 + (lid >> 4);
        const int2 c = coord[pat];
        __half* orow = g_Apack + (size_t)(m0 + pat) * KTOT + kdst;
        #pragma unroll
        for (int kc = 0; kc < 8; kc++) {             // group = two image rows
            const int y  = c.y + kc * 2 + h;
            const int x0 = c.x + 2 * jp;
            float v0 = 0.f, v1 = 0.f;
            if ((unsigned)y < HW) {
                const float* rp = imgb + y * HW;
                if ((unsigned)(x0)     < HW) v0 = __ldg(rp + x0);
                if ((unsigned)(x0 + 1) < HW) v1 = __ldg(rp + x0 + 1);
            }
            *(__half2*)(orow + kc * 32) = __floats2half2_rn(v0, v1);
        }
    }
}

// ---- kernel 2: dense GEMM out = Apack @ Wh^T + bias ----
// 256 threads, 8 warps in 2(m) x 4(n), warp tile 64x64, full K accumulated.
__global__ void __launch_bounds__(256, 1)
gemm_tc(const float* __restrict__ bias, float* __restrict__ out)
{
    extern __shared__ char smem[];
    const uint32_t sb = s2u(smem);
    const int tid = threadIdx.x;
    const int wid = tid >> 5;
    const int lid = tid & 31;
    const int m0  = blockIdx.y * BM;
    const int n0  = blockIdx.x * BN;

    const int wm = wid >> 2;             // 0..1 : 64-row group
    const int wn = wid & 3;              // 0..3 : 64-col group
    const int gq = lid >> 2;             // 0..7
    const int tq = lid & 3;              // 0..3

    // stage loader: A 128 rows x 64B, B 256 rows x 64B (k32 slice `ki`)
    #define LOAD(s, ki)                                                            \
        {                                                                          \
            _Pragma("unroll")                                                      \
            for (int i = 0; i < 2; i++) {                                          \
                const int idx = i * 256 + tid;                                     \
                const int row = idx >> 2, q = idx & 3;                             \
                cp16(sb + SM_A + (s) * A_ST + row * 64 + q * 16,                   \
                     g_Apack + (size_t)(m0 + row) * KTOT + (ki) * 32 + q * 8);     \
            }                                                                      \
            _Pragma("unroll")                                                      \
            for (int i = 0; i < 4; i++) {                                          \
                const int idx = i * 256 + tid;                                     \
                const int row = idx >> 2, q = idx & 3;                             \
                cp16(sb + SM_B + (s) * B_ST + row * 64 + q * 16,                   \
                     g_Wh + (size_t)(n0 + row) * KTOT + (ki) * 32 + q * 8);        \
            }                                                                      \
            asm volatile("cp.async.commit_group;" ::: "memory");                   \
        }

    LOAD(0, 0); LOAD(1, 1); LOAD(2, 2);

    float acc[4][8][4] = {};

    #pragma unroll 1
    for (int ki = 0; ki < NKI; ki++) {
        const int s = ki & (NST - 1);
        if (ki < NKI - 2)
            asm volatile("cp.async.wait_group 2;" ::: "memory");
        else if (ki == NKI - 2)
            asm volatile("cp.async.wait_group 1;" ::: "memory");
        else
            asm volatile("cp.async.wait_group 0;" ::: "memory");
        __syncthreads();

        if (ki + 3 < NKI) LOAD((ki + 3) & (NST - 1), ki + 3);

        const char* As = smem + SM_A + s * A_ST + (wm * 64) * 64;
        const char* Bs = smem + SM_B + s * B_ST + (wn * 64) * 64;

        uint4 alo[4], ahi[4];
        #pragma unroll
        for (int mt = 0; mt < 4; mt++) {
            alo[mt] = *(const uint4*)(As + (mt * 16 + gq) * 64 + tq * 16);
            ahi[mt] = *(const uint4*)(As + (mt * 16 + gq + 8) * 64 + tq * 16);
        }
        #pragma unroll
        for (int nt = 0; nt < 8; nt++) {
            const uint4 b = *(const uint4*)(Bs + (nt * 8 + gq) * 64 + tq * 16);
            #pragma unroll
            for (int mt = 0; mt < 4; mt++)    // k-step 0 of the group
                mma_f16(acc[mt][nt], alo[mt].x, ahi[mt].x, alo[mt].y, ahi[mt].y, b.x, b.y);
            #pragma unroll
            for (int mt = 0; mt < 4; mt++)    // k-step 1 of the group
                mma_f16(acc[mt][nt], alo[mt].z, ahi[mt].z, alo[mt].w, ahi[mt].w, b.z, b.w);
        }
    }

    // ---- epilogue: bias + float2 stores ----
    #pragma unroll
    for (int mt = 0; mt < 4; mt++) {
        const int r0 = m0 + wm * 64 + mt * 16 + gq;
        #pragma unroll
        for (int nt = 0; nt < 8; nt++) {
            const int col = n0 + wn * 64 + nt * 8 + tq * 2;
            const float2 bl = *(const float2*)(bias + col);
            float2 o0, o1;
            o0.x = acc[mt][nt][0] + bl.x;
            o0.y = acc[mt][nt][1] + bl.y;
            o1.x = acc[mt][nt][2] + bl.x;
            o1.y = acc[mt][nt][3] + bl.y;
            *(float2*)(out + (size_t)r0 * EMBD + col)       = o0;
            *(float2*)(out + (size_t)(r0 + 8) * EMBD + col) = o1;
        }
    }
}

extern "C" void kernel_launch(void* const* d_in, const int* in_sizes, int n_in,
                              void* d_out, int out_size)
{
    const float* img  = (const float*)d_in[0];   // [32,1,512,512] f32
    const int*   kp   = (const int*)  d_in[1];   // [32,4096,2] i32
    const int*   sh   = (const int*)  d_in[2];   // [32,4096,2] i32
    const float* Wlin = (const float*)d_in[3];   // [768,256] f32
    const float* blin = (const float*)d_in[4];   // [768] f32
    float*       out  = (float*)d_out;           // [32,4096,768] f32

    prep_w<<<(EMBD * KTOT + 255) / 256, 256>>>(Wlin);
    pack_a<<<(32 * TDIM) / BM, 256>>>(img, kp, sh);

    cudaFuncSetAttribute(gemm_tc,
                         cudaFuncAttributeMaxDynamicSharedMemorySize, SM_TOTAL);
    dim3 grid(EMBD / BN, (32 * TDIM) / BM);      // (3, 1024)
    gemm_tc<<<grid, 256, SM_TOTAL>>>(blin, out);
}

// round 10
// speedup vs baseline: 1.2474x; 1.0205x over previous
#include <cuda_runtime.h>
#include <cuda_fp16.h>
#include <cstdint>

// patchEmbedding: (0) W->fp16 prep, (1) patch gather/pack fp16, (2) dense fp16 HMMA GEMM.
//   M = B*T = 131072, K = 256, N = 768
// K permuted per 32-half group: pair p (0..15) stored at position 4*(p&3)+(p>>2), so a
// thread's pairs {tq, tq+4, tq+8, tq+12} are contiguous -> one LDS.128 yields fragment
// registers for TWO m16n8k16 k-steps. Stage rows are 64B, stride 64 (conflict-free).
// GEMM CTA: 128 threads, 4 warps (2m x 2n), warp tile 64x64, CTA tile 128x128,
// 3-stage cp.async ring, 2 CTAs/SM.

#define HW    512
#define TDIM  4096
#define EMBD  768
#define KTOT  256
#define BM    128
#define BN    128
#define NKI   8                            // 256 / 32 k-iterations
#define NST   3                            // cp.async stages
#define PADC  12

#define A_ST  (BM * 64)                    // 8192 B per A stage
#define B_ST  (BN * 64)                    // 8192 B per B stage
#define SM_A     0
#define SM_B     (NST * A_ST)              // 24576
#define SM_TOTAL (SM_B + NST * B_ST)       // 49152 B per CTA

__device__ __align__(16) __half g_Wh[EMBD * KTOT];        // fp16, k-permuted
__device__ __align__(16) __half g_Apack[131072 * KTOT];   // fp16, k-permuted

__device__ __forceinline__ uint32_t s2u(const void* p) {
    uint32_t a;
    asm("{ .reg .u64 t; cvta.to.shared.u64 t, %1; cvt.u32.u64 %0, t; }" : "=r"(a) : "l"(p));
    return a;
}
__device__ __forceinline__ void cp16(uint32_t dst, const void* src) {
    asm volatile("cp.async.ca.shared.global [%0], [%1], 16;" :: "r"(dst), "l"(src) : "memory");
}
__device__ __forceinline__ void mma_f16(float c[4], uint32_t a0, uint32_t a1,
                                        uint32_t a2, uint32_t a3,
                                        uint32_t b0, uint32_t b1) {
    asm volatile(
        "mma.sync.aligned.m16n8k16.row.col.f32.f16.f16.f32 "
        "{%0,%1,%2,%3}, {%4,%5,%6,%7}, {%8,%9}, {%0,%1,%2,%3};"
        : "+f"(c[0]), "+f"(c[1]), "+f"(c[2]), "+f"(c[3])
        : "r"(a0), "r"(a1), "r"(a2), "r"(a3), "r"(b0), "r"(b1));
}
// permute half index k within its 32-group: pair p=(k>>1)&15 -> 4*(p&3)+(p>>2)
__device__ __forceinline__ int kperm(int k) {
    int p = (k >> 1) & 15;
    return (k & ~31) | ((4 * (p & 3) + (p >> 2)) << 1) | (k & 1);
}

// ---- kernel 0: W -> fp16, k permuted ----
__global__ void prep_w(const float* __restrict__ W) {
    int i = blockIdx.x * blockDim.x + threadIdx.x;
    if (i >= EMBD * KTOT) return;
    g_Wh[(i & ~(KTOT - 1)) | kperm(i & (KTOT - 1))] = __float2half_rn(W[i]);
}

// ---- kernel 1: gather patches -> g_Apack (fp16, k permuted) ----
__global__ void __launch_bounds__(256, 4)
pack_a(const float* __restrict__ img,
       const int*   __restrict__ kp,
       const int*   __restrict__ sh)
{
    __shared__ int2 coord[128];
    const int tid = threadIdx.x;
    const int wid = tid >> 5;
    const int lid = tid & 31;
    const int m0  = blockIdx.x * 128;

    if (tid < 128) {
        int2 k = ((const int2*)kp)[m0 + tid];
        int2 s = ((const int2*)sh)[m0 + tid];
        int2 c;
        c.x = k.x + s.x - PADC;          // starts[...,0] = x
        c.y = k.y + s.y - PADC;          // starts[...,1] = y
        coord[tid] = c;
    }
    __syncthreads();

    const float* imgb = img + (size_t)(m0 / TDIM) * (HW * HW);
    const int pp = lid & 15;             // pair-slot within a 32-half group
    const int h  = pp >> 3;              // image-row parity within group
    const int jp = pp & 7;               // x-pair
    const int p  = h * 8 + jp;           // pair index within group
    const int kdst = (4 * (p & 3) + (p >> 2)) * 2;   // permuted half offset

    #pragma unroll 1
    for (int i = 0; i < 8; i++) {
        const int pat = i * 16 + wid * 2 + (lid >> 4);
        const int2 c = coord[pat];
        __half* orow = g_Apack + (size_t)(m0 + pat) * KTOT + kdst;
        #pragma unroll
        for (int kc = 0; kc < 8; kc++) {             // group = two image rows
            const int y  = c.y + kc * 2 + h;
            const int x0 = c.x + 2 * jp;
            float v0 = 0.f, v1 = 0.f;
            if ((unsigned)y < HW) {
                const float* rp = imgb + y * HW;
                if ((unsigned)(x0)     < HW) v0 = __ldg(rp + x0);
                if ((unsigned)(x0 + 1) < HW) v1 = __ldg(rp + x0 + 1);
            }
            *(__half2*)(orow + kc * 32) = __floats2half2_rn(v0, v1);
        }
    }
}

// ---- kernel 2: dense GEMM out = Apack @ Wh^T + bias ----
__global__ void __launch_bounds__(128, 2)
gemm_tc(const float* __restrict__ bias, float* __restrict__ out)
{
    extern __shared__ char smem[];
    const uint32_t sb = s2u(smem);
    const int tid = threadIdx.x;
    const int wid = tid >> 5;
    const int lid = tid & 31;
    const int m0  = blockIdx.y * BM;
    const int n0  = blockIdx.x * BN;

    const int wm = wid >> 1;             // 0..1 : 64-row group
    const int wn = wid & 1;              // 0..1 : 64-col group
    const int gq = lid >> 2;             // 0..7
    const int tq = lid & 3;              // 0..3

    // stage loader: A 128 rows x 64B + B 128 rows x 64B (k32 slice `ki`)
    #define LOAD(s, ki)                                                            \
        {                                                                          \
            _Pragma("unroll")                                                      \
            for (int i = 0; i < 4; i++) {                                          \
                const int idx = i * 128 + tid;                                     \
                const int row = idx >> 2, q = idx & 3;                             \
                cp16(sb + SM_A + (s) * A_ST + row * 64 + q * 16,                   \
                     g_Apack + (size_t)(m0 + row) * KTOT + (ki) * 32 + q * 8);     \
            }                                                                      \
            _Pragma("unroll")                                                      \
            for (int i = 0; i < 4; i++) {                                          \
                const int idx = i * 128 + tid;                                     \
                const int row = idx >> 2, q = idx & 3;                             \
                cp16(sb + SM_B + (s) * B_ST + row * 64 + q * 16,                   \
                     g_Wh + (size_t)(n0 + row) * KTOT + (ki) * 32 + q * 8);        \
            }                                                                      \
            asm volatile("cp.async.commit_group;" ::: "memory");                   \
        }

    LOAD(0, 0); LOAD(1, 1);

    float acc[4][8][4] = {};
    int s = 0;

    #pragma unroll 1
    for (int ki = 0; ki < NKI; ki++) {
        if (ki < NKI - 1)
            asm volatile("cp.async.wait_group 1;" ::: "memory");
        else
            asm volatile("cp.async.wait_group 0;" ::: "memory");
        __syncthreads();

        if (ki + 2 < NKI) {
            const int ns = (s + 2 >= NST) ? s + 2 - NST : s + 2;
            LOAD(ns, ki + 2);
        }

        const char* As = smem + SM_A + s * A_ST + (wm * 64) * 64;
        const char* Bs = smem + SM_B + s * B_ST + (wn * 64) * 64;

        uint4 alo[4], ahi[4];
        #pragma unroll
        for (int mt = 0; mt < 4; mt++) {
            alo[mt] = *(const uint4*)(As + (mt * 16 + gq) * 64 + tq * 16);
            ahi[mt] = *(const uint4*)(As + (mt * 16 + gq + 8) * 64 + tq * 16);
        }
        #pragma unroll
        for (int nt = 0; nt < 8; nt++) {
            const uint4 b = *(const uint4*)(Bs + (nt * 8 + gq) * 64 + tq * 16);
            #pragma unroll
            for (int mt = 0; mt < 4; mt++)    // k-step 0 of the group
                mma_f16(acc[mt][nt], alo[mt].x, ahi[mt].x, alo[mt].y, ahi[mt].y, b.x, b.y);
            #pragma unroll
            for (int mt = 0; mt < 4; mt++)    // k-step 1 of the group
                mma_f16(acc[mt][nt], alo[mt].z, ahi[mt].z, alo[mt].w, ahi[mt].w, b.z, b.w);
        }

        s = (s + 1 >= NST) ? 0 : s + 1;
    }

    // ---- epilogue: bias + float2 stores ----
    #pragma unroll
    for (int mt = 0; mt < 4; mt++) {
        const int r0 = m0 + wm * 64 + mt * 16 + gq;
        #pragma unroll
        for (int nt = 0; nt < 8; nt++) {
            const int col = n0 + wn * 64 + nt * 8 + tq * 2;
            const float2 bl = *(const float2*)(bias + col);
            float2 o0, o1;
            o0.x = acc[mt][nt][0] + bl.x;
            o0.y = acc[mt][nt][1] + bl.y;
            o1.x = acc[mt][nt][2] + bl.x;
            o1.y = acc[mt][nt][3] + bl.y;
            *(float2*)(out + (size_t)r0 * EMBD + col)       = o0;
            *(float2*)(out + (size_t)(r0 + 8) * EMBD + col) = o1;
        }
    }
}

extern "C" void kernel_launch(void* const* d_in, const int* in_sizes, int n_in,
                              void* d_out, int out_size)
{
    const float* img  = (const float*)d_in[0];   // [32,1,512,512] f32
    const int*   kp   = (const int*)  d_in[1];   // [32,4096,2] i32
    const int*   sh   = (const int*)  d_in[2];   // [32,4096,2] i32
    const float* Wlin = (const float*)d_in[3];   // [768,256] f32
    const float* blin = (const float*)d_in[4];   // [768] f32
    float*       out  = (float*)d_out;           // [32,4096,768] f32

    prep_w<<<(EMBD * KTOT + 255) / 256, 256>>>(Wlin);
    pack_a<<<(32 * TDIM) / 128, 256>>>(img, kp, sh);

    cudaFuncSetAttribute(gemm_tc,
                         cudaFuncAttributeMaxDynamicSharedMemorySize, SM_TOTAL);
    dim3 grid(EMBD / BN, (32 * TDIM) / BM);      // (6, 1024)
    gemm_tc<<<grid, 128, SM_TOTAL>>>(blin, out);
}